// round 1
// baseline (speedup 1.0000x reference)
#include <cuda_runtime.h>
#include <math.h>

// ---------------- constants ----------------
#define NB   16
#define CH   384
#define NTOK 3136            // 56*56
#define GT_OFF 19267584      // 16*3136*384

// ---------------- scratch (device globals; allocation-free) ----------------
__device__ float g_ln1[19267584];      // [B*3136, 384] dwconv+LN output
__device__ float g_h1[77070336];       // [B*3136, 1536] MLP hidden (reused as x_global later)
__device__ float g_xlocal[19267584];   // [B*3136, 384]
__device__ float g_pool1[4816896];     // [B,28,28,384]
__device__ float g_col[43352064];      // [12544, 3456] im2col
__device__ float g_c2pre[4816896];     // conv2 pre-LN
__device__ float g_c2[4816896];        // conv2 post LN+ReLU
__device__ float g_xd[1204224];        // [B,196,384]
__device__ float g_qkv[3612672];       // [B,196,1152]
__device__ float g_xds[1204224];       // [B,196,384]
__device__ float g_kv2[2408448];       // [B,196,768]
__device__ float g_qg[301056];         // [B,49,384]
__device__ float g_kv3[602112];        // [B,49,768]
__device__ float g_qx[19267584];       // [B,3136,384]
__device__ float g_w2t[1327104];       // [3456,384] transposed conv2 weight

// ---------------- helpers ----------------
__device__ __forceinline__ float gelu_exact(float x){
    return 0.5f * x * (1.0f + erff(x * 0.70710678118654752f));
}

// ---------------- SGEMM: C[M,N] = A[M,K] @ B[K,N] (+ epilogue) ----------------
// MODE 0: C = A@B
// MODE 1: C = A@B + bias
// MODE 2: C = gelu(A@B + bias)
// MODE 3: C = (A@B + bias) * gamma + res
// MODE 4: C = (A + A2)@B + bias
// Requires: K % 8 == 0, N % 128 == 0 (M guarded).
template<int MODE>
__global__ __launch_bounds__(256) void sgemm_kernel(
    const float* __restrict__ A, const float* __restrict__ A2,
    const float* __restrict__ B, const float* __restrict__ bias,
    const float* __restrict__ gamma, const float* __restrict__ res,
    float* __restrict__ Cout, int M, int N, int K)
{
    __shared__ float As[8][128];
    __shared__ float Bs[8][128];
    const int tid = threadIdx.x;
    const int bm = blockIdx.y * 128;
    const int bn = blockIdx.x * 128;
    const int tx = tid & 15, ty = tid >> 4;
    const int a_r = tid >> 1, a_c = (tid & 1) << 2;
    const int b_r = tid >> 5, b_c = (tid & 31) << 2;

    float acc[8][8];
    #pragma unroll
    for (int i = 0; i < 8; i++)
        #pragma unroll
        for (int j = 0; j < 8; j++) acc[i][j] = 0.f;

    const bool a_valid = (bm + a_r) < M;
    const float* Ap  = A  + (size_t)(bm + a_r) * K + a_c;
    const float* A2p = (MODE == 4) ? (A2 + (size_t)(bm + a_r) * K + a_c) : nullptr;
    const float* Bp  = B + (size_t)b_r * N + bn + b_c;

    for (int k0 = 0; k0 < K; k0 += 8) {
        float4 av = make_float4(0.f, 0.f, 0.f, 0.f);
        if (a_valid) {
            av = *(const float4*)Ap;
            if (MODE == 4) {
                float4 a2 = *(const float4*)A2p;
                av.x += a2.x; av.y += a2.y; av.z += a2.z; av.w += a2.w;
            }
        }
        float4 bv = *(const float4*)Bp;
        __syncthreads();
        As[a_c + 0][a_r] = av.x; As[a_c + 1][a_r] = av.y;
        As[a_c + 2][a_r] = av.z; As[a_c + 3][a_r] = av.w;
        *(float4*)&Bs[b_r][b_c] = bv;
        __syncthreads();
        #pragma unroll
        for (int kk = 0; kk < 8; kk++) {
            float4 a0 = *(const float4*)&As[kk][ty * 8];
            float4 a1 = *(const float4*)&As[kk][ty * 8 + 4];
            float4 b0 = *(const float4*)&Bs[kk][tx * 8];
            float4 b1 = *(const float4*)&Bs[kk][tx * 8 + 4];
            float ra[8] = {a0.x, a0.y, a0.z, a0.w, a1.x, a1.y, a1.z, a1.w};
            float rb[8] = {b0.x, b0.y, b0.z, b0.w, b1.x, b1.y, b1.z, b1.w};
            #pragma unroll
            for (int i = 0; i < 8; i++)
                #pragma unroll
                for (int j = 0; j < 8; j++)
                    acc[i][j] = fmaf(ra[i], rb[j], acc[i][j]);
        }
        Ap += 8;
        if (MODE == 4) A2p += 8;
        Bp += (size_t)8 * N;
    }

    #pragma unroll
    for (int i = 0; i < 8; i++) {
        int row = bm + ty * 8 + i;
        if (row >= M) continue;
        float* crow = Cout + (size_t)row * N + bn + tx * 8;
        const float* rrow = (MODE == 3) ? (res + (size_t)row * N + bn + tx * 8) : nullptr;
        #pragma unroll
        for (int j = 0; j < 8; j++) {
            int col = bn + tx * 8 + j;
            float val = acc[i][j];
            if (MODE >= 1) val += bias[col];
            if (MODE == 2) val = gelu_exact(val);
            if (MODE == 3) val = val * gamma[col] + rrow[j];
            crow[j] = val;
        }
    }
}

// ---------------- dwconv 3x3 (depthwise, SAME) + LayerNorm(eps=1e-6) ----------------
// one block per pixel, 128 threads, 3 channels each
__global__ void dwconv_ln_kernel(const float* __restrict__ x,
                                 const float* __restrict__ dw, const float* __restrict__ db,
                                 const float* __restrict__ gam, const float* __restrict__ bet,
                                 float* __restrict__ out)
{
    __shared__ float sred[64];
    const int pix = blockIdx.x;
    const int b = pix / 3136, hw = pix % 3136;
    const int h = hw / 56, w = hw % 56;
    const int tid = threadIdx.x;
    float v[3];
    float s = 0.f, s2 = 0.f;
    #pragma unroll
    for (int r = 0; r < 3; r++) {
        int c = tid + r * 128;
        float acc = db[c];
        #pragma unroll
        for (int ky = 0; ky < 3; ky++) {
            int hh = h + ky - 1;
            if ((unsigned)hh >= 56u) continue;
            #pragma unroll
            for (int kx = 0; kx < 3; kx++) {
                int ww = w + kx - 1;
                if ((unsigned)ww >= 56u) continue;
                acc = fmaf(x[((size_t)b * 3136 + hh * 56 + ww) * 384 + c],
                           dw[c * 9 + ky * 3 + kx], acc);
            }
        }
        v[r] = acc; s += acc; s2 = fmaf(acc, acc, s2);
    }
    int lane = tid & 31, warp = tid >> 5;
    #pragma unroll
    for (int off = 16; off; off >>= 1) {
        s  += __shfl_xor_sync(0xffffffffu, s, off);
        s2 += __shfl_xor_sync(0xffffffffu, s2, off);
    }
    if (lane == 0) { sred[warp] = s; sred[warp + 32] = s2; }
    __syncthreads();
    if (warp == 0) {
        float a  = (lane < 4) ? sred[lane] : 0.f;
        float b2 = (lane < 4) ? sred[lane + 32] : 0.f;
        #pragma unroll
        for (int off = 2; off; off >>= 1) {
            a  += __shfl_xor_sync(0xffffffffu, a, off);
            b2 += __shfl_xor_sync(0xffffffffu, b2, off);
        }
        if (lane == 0) { sred[0] = a; sred[1] = b2; }
    }
    __syncthreads();
    float mean = sred[0] * (1.f / 384.f);
    float var  = sred[1] * (1.f / 384.f) - mean * mean;
    float rstd = rsqrtf(var + 1e-6f);
    #pragma unroll
    for (int r = 0; r < 3; r++) {
        int c = tid + r * 128;
        out[(size_t)pix * 384 + c] = (v[r] - mean) * rstd * gam[c] + bet[c];
    }
}

// ---------------- LayerNorm (+optional ReLU) over 384 channels ----------------
__global__ void ln_act_kernel(const float* __restrict__ in, const float* __restrict__ gam,
                              const float* __restrict__ bet, float* __restrict__ out,
                              float eps, int do_relu)
{
    __shared__ float sred[64];
    const size_t pix = blockIdx.x;
    const int tid = threadIdx.x;
    float v[3];
    float s = 0.f, s2 = 0.f;
    #pragma unroll
    for (int r = 0; r < 3; r++) {
        float a = in[pix * 384 + tid + r * 128];
        v[r] = a; s += a; s2 = fmaf(a, a, s2);
    }
    int lane = tid & 31, warp = tid >> 5;
    #pragma unroll
    for (int off = 16; off; off >>= 1) {
        s  += __shfl_xor_sync(0xffffffffu, s, off);
        s2 += __shfl_xor_sync(0xffffffffu, s2, off);
    }
    if (lane == 0) { sred[warp] = s; sred[warp + 32] = s2; }
    __syncthreads();
    if (warp == 0) {
        float a  = (lane < 4) ? sred[lane] : 0.f;
        float b2 = (lane < 4) ? sred[lane + 32] : 0.f;
        #pragma unroll
        for (int off = 2; off; off >>= 1) {
            a  += __shfl_xor_sync(0xffffffffu, a, off);
            b2 += __shfl_xor_sync(0xffffffffu, b2, off);
        }
        if (lane == 0) { sred[0] = a; sred[1] = b2; }
    }
    __syncthreads();
    float mean = sred[0] * (1.f / 384.f);
    float var  = sred[1] * (1.f / 384.f) - mean * mean;
    float rstd = rsqrtf(var + eps);
    #pragma unroll
    for (int r = 0; r < 3; r++) {
        int c = tid + r * 128;
        float val = (v[r] - mean) * rstd * gam[c] + bet[c];
        if (do_relu) val = fmaxf(val, 0.f);
        out[pix * 384 + c] = val;
    }
}

// ---------------- AvgPool2d(2,2) in NHWC ----------------
__global__ void avgpool2_kernel(const float* __restrict__ in, float* __restrict__ out,
                                int B_, int Ho, int Wo)
{
    int idx = blockIdx.x * blockDim.x + threadIdx.x;
    int total = B_ * Ho * Wo * 384;
    if (idx >= total) return;
    int c = idx % 384; int t = idx / 384;
    int wo = t % Wo; t /= Wo;
    int ho = t % Ho; int b = t / Ho;
    int Hi = Ho * 2, Wi = Wo * 2;
    const float* p = in + (((size_t)b * Hi + 2 * ho) * Wi + 2 * wo) * 384 + c;
    out[idx] = 0.25f * (p[0] + p[384] + p[(size_t)Wi * 384] + p[(size_t)Wi * 384 + 384]);
}

// ---------------- im2col for 3x3 SAME conv at 28x28, NHWC ----------------
__global__ void im2col_kernel(const float* __restrict__ in, float* __restrict__ out)
{
    long long idx = (long long)blockIdx.x * blockDim.x + threadIdx.x;
    if (idx >= 12544LL * 3456LL) return;
    int j = (int)(idx % 3456); int pix = (int)(idx / 3456);
    int c = j % 384; int kk = j / 384;
    int ky = kk / 3, kx = kk % 3;
    int w = pix % 28; int t = pix / 28;
    int h = t % 28; int b = t / 28;
    int hh = h + ky - 1, ww = w + kx - 1;
    float val = 0.f;
    if ((unsigned)hh < 28u && (unsigned)ww < 28u)
        val = in[(((size_t)b * 28 + hh) * 28 + ww) * 384 + c];
    out[idx] = val;
}

// ---------------- conv2 weight transpose [O,I,3,3] -> [(ky*3+kx)*384+i, O] ----------------
__global__ void wtrans_kernel(const float* __restrict__ w, float* __restrict__ out)
{
    int idx = blockIdx.x * blockDim.x + threadIdx.x;
    if (idx >= 3456 * 384) return;
    int o = idx % 384; int r = idx / 384;
    int i = r % 384; int kk = r / 384;
    out[idx] = w[((size_t)o * 384 + i) * 9 + kk];
}

// ---------------- MHA: one warp per query, K/V staged in dynamic smem ----------------
// q/k/v row strides in elements; head dim 64, 6 heads. scale 0.125 applied to q.
__global__ void mha_kernel(const float* __restrict__ q, int qs,
                           const float* __restrict__ k, int ks,
                           const float* __restrict__ v, int vs,
                           float* __restrict__ o, int os,
                           int Nq, int Nk)
{
    extern __shared__ float sm[];
    float* ksh = sm;
    float* vsh = sm + (size_t)Nk * 64;
    float* ssc = vsh + (size_t)Nk * 64;
    const int bh = blockIdx.x;
    const int b = bh / 6, h = bh % 6;
    const int tid = threadIdx.x;
    const int warp = tid >> 5, lane = tid & 31;
    const float* kb = k + (size_t)b * Nk * ks + h * 64;
    const float* vb = v + (size_t)b * Nk * vs + h * 64;
    for (int idx = tid; idx < Nk * 64; idx += blockDim.x) {
        int j = idx >> 6, d = idx & 63;
        ksh[idx] = kb[(size_t)j * ks + d];
        vsh[idx] = vb[(size_t)j * vs + d];
    }
    __syncthreads();
    const int nw = blockDim.x >> 5;
    float* sc = ssc + warp * Nk;
    const int d0 = lane << 1;
    for (int qi = blockIdx.y * nw + warp; qi < Nq; qi += gridDim.y * nw) {
        const float* qr = q + ((size_t)b * Nq + qi) * qs + h * 64;
        float q0 = qr[d0] * 0.125f, q1 = qr[d0 + 1] * 0.125f;
        float mx = -1e30f;
        for (int j = 0; j < Nk; j++) {
            float s = fmaf(q0, ksh[(j << 6) + d0], q1 * ksh[(j << 6) + d0 + 1]);
            #pragma unroll
            for (int off = 16; off; off >>= 1) s += __shfl_xor_sync(0xffffffffu, s, off);
            if (lane == (j & 31)) sc[j] = s;
            mx = fmaxf(mx, s);
        }
        __syncwarp();
        float sume = 0.f;
        for (int j = lane; j < Nk; j += 32) {
            float e = expf(sc[j] - mx);
            sc[j] = e; sume += e;
        }
        #pragma unroll
        for (int off = 16; off; off >>= 1) sume += __shfl_xor_sync(0xffffffffu, sume, off);
        float inv = 1.f / sume;
        __syncwarp();
        float o0 = 0.f, o1 = 0.f;
        for (int j = 0; j < Nk; j++) {
            float p = sc[j];
            o0 = fmaf(p, vsh[(j << 6) + d0], o0);
            o1 = fmaf(p, vsh[(j << 6) + d0 + 1], o1);
        }
        float* orow = o + ((size_t)b * Nq + qi) * os + h * 64;
        orow[d0] = o0 * inv;
        orow[d0 + 1] = o1 * inv;
        __syncwarp();
    }
}

// ---------------- launch ----------------
extern "C" void kernel_launch(void* const* d_in, const int* in_sizes, int n_in,
                              void* d_out, int out_size)
{
    const float* x        = (const float*)d_in[0];
    const float* gtok     = (const float*)d_in[1];
    const float* we_dw_w  = (const float*)d_in[2];
    const float* we_dw_b  = (const float*)d_in[3];
    const float* we_ln_g  = (const float*)d_in[4];
    const float* we_ln_b  = (const float*)d_in[5];
    const float* we_pw1_w = (const float*)d_in[6];
    const float* we_pw1_b = (const float*)d_in[7];
    const float* we_pw2_w = (const float*)d_in[8];
    const float* we_pw2_b = (const float*)d_in[9];
    const float* we_gamma = (const float*)d_in[10];
    const float* cb_conv_w= (const float*)d_in[11];
    const float* cb_ln_g  = (const float*)d_in[12];
    const float* cb_ln_b  = (const float*)d_in[13];
    const float* ga_qkv_w = (const float*)d_in[14];
    const float* ug_kv_w  = (const float*)d_in[15];
    const float* ug_q_w   = (const float*)d_in[16];
    const float* gb_kv_w  = (const float*)d_in[17];
    const float* gb_q_w   = (const float*)d_in[18];
    const float* proj_w   = (const float*)d_in[19];
    const float* proj_b   = (const float*)d_in[20];

    float* out = (float*)d_out;
    float* gt_out = out + GT_OFF;

    float *ln1, *h1, *xlocal, *pool1, *col, *c2pre, *c2, *xd, *qkv, *xds, *kv2, *qg, *kv3, *qx, *w2t;
    cudaGetSymbolAddress((void**)&ln1,    g_ln1);
    cudaGetSymbolAddress((void**)&h1,     g_h1);
    cudaGetSymbolAddress((void**)&xlocal, g_xlocal);
    cudaGetSymbolAddress((void**)&pool1,  g_pool1);
    cudaGetSymbolAddress((void**)&col,    g_col);
    cudaGetSymbolAddress((void**)&c2pre,  g_c2pre);
    cudaGetSymbolAddress((void**)&c2,     g_c2);
    cudaGetSymbolAddress((void**)&xd,     g_xd);
    cudaGetSymbolAddress((void**)&qkv,    g_qkv);
    cudaGetSymbolAddress((void**)&xds,    g_xds);
    cudaGetSymbolAddress((void**)&kv2,    g_kv2);
    cudaGetSymbolAddress((void**)&qg,     g_qg);
    cudaGetSymbolAddress((void**)&kv3,    g_kv3);
    cudaGetSymbolAddress((void**)&qx,     g_qx);
    cudaGetSymbolAddress((void**)&w2t,    g_w2t);
    float* xglobal = h1;   // reuse MLP hidden buffer (free after MLP2)

    const int SMEM196 = 196 * 128 * 4 + 4 * 196 * 4;  // 103488 B
    const int SMEM49  = 49  * 128 * 4 + 4 * 49  * 4;  // 25872  B
    cudaFuncSetAttribute(mha_kernel, cudaFuncAttributeMaxDynamicSharedMemorySize, SMEM196);

    // conv2 weight transpose (tiny)
    wtrans_kernel<<<(3456 * 384 + 255) / 256, 256>>>(cb_conv_w, w2t);

    // ConvEncoder: dwconv + LN
    dwconv_ln_kernel<<<50176, 128>>>(x, we_dw_w, we_dw_b, we_ln_g, we_ln_b, ln1);

    // MLP1: gelu(ln1 @ pw1 + b1)  [50176,384]@[384,1536]
    sgemm_kernel<2><<<dim3(1536 / 128, 392), 256>>>(ln1, nullptr, we_pw1_w, we_pw1_b,
                                                    nullptr, nullptr, h1, 50176, 1536, 384);
    // MLP2 + layer-scale + residual: (h1 @ pw2 + b2)*gamma + x
    sgemm_kernel<3><<<dim3(384 / 128, 392), 256>>>(h1, nullptr, we_pw2_w, we_pw2_b,
                                                   we_gamma, x, xlocal, 50176, 384, 1536);
    // down_1: 56->28
    avgpool2_kernel<<<(4816896 + 255) / 256, 256>>>(xlocal, pool1, 16, 28, 28);

    // ConvBNReLU: im2col + GEMM + LN(1e-5) + ReLU
    im2col_kernel<<<(int)((12544LL * 3456 + 255) / 256), 256>>>(pool1, col);
    sgemm_kernel<0><<<dim3(3, 98), 256>>>(col, nullptr, w2t, nullptr, nullptr, nullptr,
                                          c2pre, 12544, 384, 3456);
    ln_act_kernel<<<12544, 128>>>(c2pre, cb_ln_g, cb_ln_b, c2, 1e-5f, 1);

    // down_2: 28->14
    avgpool2_kernel<<<(1204224 + 255) / 256, 256>>>(c2, xd, 16, 14, 14);

    // global aggregation MHSA
    sgemm_kernel<0><<<dim3(9, 25), 256>>>(xd, nullptr, ga_qkv_w, nullptr, nullptr, nullptr,
                                          qkv, 3136, 1152, 384);
    mha_kernel<<<dim3(96, 8), 128, SMEM196>>>(qkv, 1152, qkv + 384, 1152, qkv + 768, 1152,
                                              xds, 384, 196, 196);

    // global token update
    sgemm_kernel<0><<<dim3(6, 25), 256>>>(xds, nullptr, ug_kv_w, nullptr, nullptr, nullptr,
                                          kv2, 3136, 768, 384);
    sgemm_kernel<0><<<dim3(3, 7), 256>>>(gtok, nullptr, ug_q_w, nullptr, nullptr, nullptr,
                                         qg, 784, 384, 384);
    mha_kernel<<<dim3(96, 2), 128, SMEM196>>>(qg, 384, kv2, 768, kv2 + 384, 768,
                                              gt_out, 384, 49, 196);   // gt -> output tail

    // global broadcast
    sgemm_kernel<0><<<dim3(6, 7), 256>>>(gt_out, nullptr, gb_kv_w, nullptr, nullptr, nullptr,
                                         kv3, 784, 768, 384);
    sgemm_kernel<0><<<dim3(3, 392), 256>>>(x, nullptr, gb_q_w, nullptr, nullptr, nullptr,
                                           qx, 50176, 384, 384);
    mha_kernel<<<dim3(96, 64), 128, SMEM49>>>(qx, 384, kv3, 768, kv3 + 384, 768,
                                              xglobal, 384, 3136, 49);

    // final projection: (x_local + x_global) @ proj_w + proj_b -> out
    sgemm_kernel<4><<<dim3(3, 392), 256>>>(xlocal, xglobal, proj_w, proj_b,
                                           nullptr, nullptr, out, 50176, 384, 384);
}

// round 2
// speedup vs baseline: 1.8714x; 1.8714x over previous
#include <cuda_runtime.h>
#include <math.h>

// ---------------- constants ----------------
#define GT_OFF 19267584      // 16*3136*384

// ---------------- scratch (device globals; allocation-free) ----------------
__device__ float g_ln1[19267584];      // [B*3136, 384] dwconv+LN output
__device__ float g_h1[77070336];       // [B*3136, 1536] MLP hidden (reused as x_global later)
__device__ float g_xlocal[19267584];   // [B*3136, 384]
__device__ float g_pool1[4816896];     // [B,28,28,384]
__device__ float g_col[43352064];      // [12544, 3456] im2col
__device__ float g_c2pre[4816896];     // conv2 pre-LN
__device__ float g_c2[4816896];        // conv2 post LN+ReLU
__device__ float g_xd[1204224];        // [B,196,384]
__device__ float g_qkv[3612672];       // [B,196,1152]
__device__ float g_xds[1204224];       // [B,196,384]
__device__ float g_kv2[2408448];       // [B,196,768]
__device__ float g_qg[301056];         // [B,49,384]
__device__ float g_kv3[602112];        // [B,49,768]
__device__ float g_qx[19267584];       // [B,3136,384]
// transposed weights [N,K]
__device__ float g_pw1T[589824];       // [1536,384]
__device__ float g_pw2T[589824];       // [384,1536]
__device__ float g_qkvT[442368];       // [1152,384]
__device__ float g_ugkvT[294912];      // [768,384]
__device__ float g_ugqT[147456];       // [384,384]
__device__ float g_gbkvT[294912];      // [768,384]
__device__ float g_gbqT[147456];       // [384,384]
__device__ float g_projT[147456];      // [384,384]
__device__ float g_convT[1327104];     // [384,3456]

// ---------------- helpers ----------------
__device__ __forceinline__ float gelu_exact(float x){
    return 0.5f * x * (1.0f + erff(x * 0.70710678118654752f));
}
__device__ __forceinline__ unsigned f2t(float x){
    unsigned u; asm("cvt.rna.tf32.f32 %0, %1;" : "=r"(u) : "f"(x)); return u;
}
__device__ __forceinline__ void mma8(float* d, const unsigned* a, const unsigned* b){
    asm volatile("mma.sync.aligned.m16n8k8.row.col.f32.tf32.tf32.f32 "
        "{%0,%1,%2,%3},{%4,%5,%6,%7},{%8,%9},{%0,%1,%2,%3};"
        : "+f"(d[0]), "+f"(d[1]), "+f"(d[2]), "+f"(d[3])
        : "r"(a[0]), "r"(a[1]), "r"(a[2]), "r"(a[3]), "r"(b[0]), "r"(b[1]));
}

// ---------------- TF32 tensor GEMM: C[M,N] = A[M,K] @ B[K,N] ----------------
// BT is B transposed: [N,K] row-major. K%16==0, N%128==0; M guarded.
// MODE 0: C = A@B
// MODE 2: C = gelu(A@B + bias)
// MODE 3: C = (A@B + bias)*gamma + res
// MODE 4: C = (A + A2)@B + bias
template<int MODE>
__global__ void __launch_bounds__(256) tgemm_kernel(
    const float* __restrict__ A, const float* __restrict__ A2,
    const float* __restrict__ BT, const float* __restrict__ bias,
    const float* __restrict__ gamma, const float* __restrict__ res,
    float* __restrict__ C, int M, int N, int K)
{
    __shared__ unsigned As[2][128][20];
    __shared__ unsigned Bs[2][128][20];
    const int tid  = threadIdx.x;
    const int warp = tid >> 5, lane = tid & 31;
    const int wm = (warp >> 2) * 64;   // warp row offset within tile
    const int wn = (warp & 3) * 32;    // warp col offset within tile
    const int bm = blockIdx.y * 128;
    const int bn = blockIdx.x * 128;

    float acc[4][4][4];
    #pragma unroll
    for (int t = 0; t < 4; t++)
        #pragma unroll
        for (int u = 0; u < 4; u++)
            #pragma unroll
            for (int e = 0; e < 4; e++) acc[t][u][e] = 0.f;

    // global-load mapping: 128 rows x 16 cols per tile, float4 per thread x2
    const int lr0 = tid >> 2;          // rows 0..63
    const int lr1 = lr0 + 64;          // rows 64..127
    const int lkc = (tid & 3) << 2;    // k col 0,4,8,12

    const bool va0 = (bm + lr0) < M;
    const bool va1 = (bm + lr1) < M;
    const float* Ap0 = A + (size_t)(bm + lr0) * K + lkc;
    const float* Ap1 = A + (size_t)(bm + lr1) * K + lkc;
    const float* A2p0 = (MODE == 4) ? A2 + (size_t)(bm + lr0) * K + lkc : nullptr;
    const float* A2p1 = (MODE == 4) ? A2 + (size_t)(bm + lr1) * K + lkc : nullptr;
    const float* Bp0 = BT + (size_t)(bn + lr0) * K + lkc;
    const float* Bp1 = BT + (size_t)(bn + lr1) * K + lkc;

    const int T = K >> 4;

    // ---- preload tile 0 ----
    float4 fa0 = make_float4(0,0,0,0), fa1 = make_float4(0,0,0,0);
    if (va0) {
        fa0 = *(const float4*)Ap0;
        if (MODE == 4) { float4 t2 = *(const float4*)A2p0; fa0.x+=t2.x; fa0.y+=t2.y; fa0.z+=t2.z; fa0.w+=t2.w; }
    }
    if (va1) {
        fa1 = *(const float4*)Ap1;
        if (MODE == 4) { float4 t2 = *(const float4*)A2p1; fa1.x+=t2.x; fa1.y+=t2.y; fa1.z+=t2.z; fa1.w+=t2.w; }
    }
    float4 fb0 = *(const float4*)Bp0;
    float4 fb1 = *(const float4*)Bp1;
    *(uint4*)&As[0][lr0][lkc] = make_uint4(f2t(fa0.x), f2t(fa0.y), f2t(fa0.z), f2t(fa0.w));
    *(uint4*)&As[0][lr1][lkc] = make_uint4(f2t(fa1.x), f2t(fa1.y), f2t(fa1.z), f2t(fa1.w));
    *(uint4*)&Bs[0][lr0][lkc] = make_uint4(f2t(fb0.x), f2t(fb0.y), f2t(fb0.z), f2t(fb0.w));
    *(uint4*)&Bs[0][lr1][lkc] = make_uint4(f2t(fb1.x), f2t(fb1.y), f2t(fb1.z), f2t(fb1.w));
    __syncthreads();

    #pragma unroll 1
    for (int it = 0; it < T; ++it) {
        const int buf = it & 1;
        // prefetch next tile into registers
        float4 na0, na1, nb0, nb1;
        if (it + 1 < T) {
            const int ko = (it + 1) << 4;
            na0 = make_float4(0,0,0,0); na1 = make_float4(0,0,0,0);
            if (va0) {
                na0 = *(const float4*)(Ap0 + ko);
                if (MODE == 4) { float4 t2 = *(const float4*)(A2p0 + ko); na0.x+=t2.x; na0.y+=t2.y; na0.z+=t2.z; na0.w+=t2.w; }
            }
            if (va1) {
                na1 = *(const float4*)(Ap1 + ko);
                if (MODE == 4) { float4 t2 = *(const float4*)(A2p1 + ko); na1.x+=t2.x; na1.y+=t2.y; na1.z+=t2.z; na1.w+=t2.w; }
            }
            nb0 = *(const float4*)(Bp0 + ko);
            nb1 = *(const float4*)(Bp1 + ko);
        }
        // compute on buf
        #pragma unroll
        for (int ks = 0; ks < 16; ks += 8) {
            unsigned af[4][4], bf[4][2];
            const int kq = ks + (lane & 3);
            const int rq = lane >> 2;
            #pragma unroll
            for (int t = 0; t < 4; t++) {
                const int ar = wm + t * 16 + rq;
                af[t][0] = As[buf][ar    ][kq];
                af[t][1] = As[buf][ar + 8][kq];
                af[t][2] = As[buf][ar    ][kq + 4];
                af[t][3] = As[buf][ar + 8][kq + 4];
            }
            #pragma unroll
            for (int u = 0; u < 4; u++) {
                const int br = wn + u * 8 + rq;
                bf[u][0] = Bs[buf][br][kq];
                bf[u][1] = Bs[buf][br][kq + 4];
            }
            #pragma unroll
            for (int t = 0; t < 4; t++)
                #pragma unroll
                for (int u = 0; u < 4; u++)
                    mma8(acc[t][u], af[t], bf[u]);
        }
        // stage next tile
        if (it + 1 < T) {
            const int nb = buf ^ 1;
            *(uint4*)&As[nb][lr0][lkc] = make_uint4(f2t(na0.x), f2t(na0.y), f2t(na0.z), f2t(na0.w));
            *(uint4*)&As[nb][lr1][lkc] = make_uint4(f2t(na1.x), f2t(na1.y), f2t(na1.z), f2t(na1.w));
            *(uint4*)&Bs[nb][lr0][lkc] = make_uint4(f2t(nb0.x), f2t(nb0.y), f2t(nb0.z), f2t(nb0.w));
            *(uint4*)&Bs[nb][lr1][lkc] = make_uint4(f2t(nb1.x), f2t(nb1.y), f2t(nb1.z), f2t(nb1.w));
        }
        __syncthreads();
    }

    // ---- epilogue ----
    #pragma unroll
    for (int t = 0; t < 4; t++) {
        const int row0 = bm + wm + t * 16 + (lane >> 2);
        const int row1 = row0 + 8;
        #pragma unroll
        for (int u = 0; u < 4; u++) {
            const int col = bn + wn + u * 8 + ((lane & 3) << 1);
            float b0 = 0.f, b1 = 0.f;
            if (MODE == 2 || MODE == 3 || MODE == 4) { b0 = bias[col]; b1 = bias[col + 1]; }
            #pragma unroll
            for (int h = 0; h < 2; h++) {
                const int row = h ? row1 : row0;
                if (row >= M) continue;
                float v0 = acc[t][u][h * 2 + 0] + b0;
                float v1 = acc[t][u][h * 2 + 1] + b1;
                if (MODE == 2) { v0 = gelu_exact(v0); v1 = gelu_exact(v1); }
                if (MODE == 3) {
                    const float* rr = res + (size_t)row * N + col;
                    v0 = v0 * gamma[col]     + rr[0];
                    v1 = v1 * gamma[col + 1] + rr[1];
                }
                float2 o = make_float2(v0, v1);
                *(float2*)&C[(size_t)row * N + col] = o;
            }
        }
    }
}

// ---------------- weight transpose: in[K][N] -> out[N][K] ----------------
__global__ void transpose_kernel(const float* __restrict__ in, float* __restrict__ out,
                                 int K, int N)
{
    int idx = blockIdx.x * blockDim.x + threadIdx.x;
    if (idx >= K * N) return;
    int n = idx / K, k = idx % K;
    out[idx] = in[(size_t)k * N + n];
}

// conv weight: [O=384, I=384, 3, 3] -> out[o][kk*384+i]
__global__ void convw_trans_kernel(const float* __restrict__ w, float* __restrict__ out)
{
    int idx = blockIdx.x * blockDim.x + threadIdx.x;
    if (idx >= 384 * 3456) return;
    int o = idx / 3456, j = idx % 3456;
    int kk = j / 384, i = j % 384;
    out[idx] = w[(size_t)o * 3456 + i * 9 + kk];
}

// ---------------- dwconv 3x3 (depthwise, SAME) + LayerNorm(eps=1e-6) ----------------
__global__ void dwconv_ln_kernel(const float* __restrict__ x,
                                 const float* __restrict__ dw, const float* __restrict__ db,
                                 const float* __restrict__ gam, const float* __restrict__ bet,
                                 float* __restrict__ out)
{
    __shared__ float sred[64];
    const int pix = blockIdx.x;
    const int b = pix / 3136, hw = pix % 3136;
    const int h = hw / 56, w = hw % 56;
    const int tid = threadIdx.x;
    float v[3];
    float s = 0.f, s2 = 0.f;
    #pragma unroll
    for (int r = 0; r < 3; r++) {
        int c = tid + r * 128;
        float acc = db[c];
        #pragma unroll
        for (int ky = 0; ky < 3; ky++) {
            int hh = h + ky - 1;
            if ((unsigned)hh >= 56u) continue;
            #pragma unroll
            for (int kx = 0; kx < 3; kx++) {
                int ww = w + kx - 1;
                if ((unsigned)ww >= 56u) continue;
                acc = fmaf(x[((size_t)b * 3136 + hh * 56 + ww) * 384 + c],
                           dw[c * 9 + ky * 3 + kx], acc);
            }
        }
        v[r] = acc; s += acc; s2 = fmaf(acc, acc, s2);
    }
    int lane = tid & 31, warp = tid >> 5;
    #pragma unroll
    for (int off = 16; off; off >>= 1) {
        s  += __shfl_xor_sync(0xffffffffu, s, off);
        s2 += __shfl_xor_sync(0xffffffffu, s2, off);
    }
    if (lane == 0) { sred[warp] = s; sred[warp + 32] = s2; }
    __syncthreads();
    if (warp == 0) {
        float a  = (lane < 4) ? sred[lane] : 0.f;
        float b2 = (lane < 4) ? sred[lane + 32] : 0.f;
        #pragma unroll
        for (int off = 2; off; off >>= 1) {
            a  += __shfl_xor_sync(0xffffffffu, a, off);
            b2 += __shfl_xor_sync(0xffffffffu, b2, off);
        }
        if (lane == 0) { sred[0] = a; sred[1] = b2; }
    }
    __syncthreads();
    float mean = sred[0] * (1.f / 384.f);
    float var  = sred[1] * (1.f / 384.f) - mean * mean;
    float rstd = rsqrtf(var + 1e-6f);
    #pragma unroll
    for (int r = 0; r < 3; r++) {
        int c = tid + r * 128;
        out[(size_t)pix * 384 + c] = (v[r] - mean) * rstd * gam[c] + bet[c];
    }
}

// ---------------- LayerNorm (+optional ReLU) over 384 channels ----------------
__global__ void ln_act_kernel(const float* __restrict__ in, const float* __restrict__ gam,
                              const float* __restrict__ bet, float* __restrict__ out,
                              float eps, int do_relu)
{
    __shared__ float sred[64];
    const size_t pix = blockIdx.x;
    const int tid = threadIdx.x;
    float v[3];
    float s = 0.f, s2 = 0.f;
    #pragma unroll
    for (int r = 0; r < 3; r++) {
        float a = in[pix * 384 + tid + r * 128];
        v[r] = a; s += a; s2 = fmaf(a, a, s2);
    }
    int lane = tid & 31, warp = tid >> 5;
    #pragma unroll
    for (int off = 16; off; off >>= 1) {
        s  += __shfl_xor_sync(0xffffffffu, s, off);
        s2 += __shfl_xor_sync(0xffffffffu, s2, off);
    }
    if (lane == 0) { sred[warp] = s; sred[warp + 32] = s2; }
    __syncthreads();
    if (warp == 0) {
        float a  = (lane < 4) ? sred[lane] : 0.f;
        float b2 = (lane < 4) ? sred[lane + 32] : 0.f;
        #pragma unroll
        for (int off = 2; off; off >>= 1) {
            a  += __shfl_xor_sync(0xffffffffu, a, off);
            b2 += __shfl_xor_sync(0xffffffffu, b2, off);
        }
        if (lane == 0) { sred[0] = a; sred[1] = b2; }
    }
    __syncthreads();
    float mean = sred[0] * (1.f / 384.f);
    float var  = sred[1] * (1.f / 384.f) - mean * mean;
    float rstd = rsqrtf(var + eps);
    #pragma unroll
    for (int r = 0; r < 3; r++) {
        int c = tid + r * 128;
        float val = (v[r] - mean) * rstd * gam[c] + bet[c];
        if (do_relu) val = fmaxf(val, 0.f);
        out[pix * 384 + c] = val;
    }
}

// ---------------- AvgPool2d(2,2) in NHWC ----------------
__global__ void avgpool2_kernel(const float* __restrict__ in, float* __restrict__ out,
                                int B_, int Ho, int Wo)
{
    int idx = blockIdx.x * blockDim.x + threadIdx.x;
    int total = B_ * Ho * Wo * 384;
    if (idx >= total) return;
    int c = idx % 384; int t = idx / 384;
    int wo = t % Wo; t /= Wo;
    int ho = t % Ho; int b = t / Ho;
    int Hi = Ho * 2, Wi = Wo * 2;
    const float* p = in + (((size_t)b * Hi + 2 * ho) * Wi + 2 * wo) * 384 + c;
    out[idx] = 0.25f * (p[0] + p[384] + p[(size_t)Wi * 384] + p[(size_t)Wi * 384 + 384]);
}

// ---------------- im2col for 3x3 SAME conv at 28x28, NHWC ----------------
__global__ void im2col_kernel(const float* __restrict__ in, float* __restrict__ out)
{
    long long idx = (long long)blockIdx.x * blockDim.x + threadIdx.x;
    if (idx >= 12544LL * 3456LL) return;
    int j = (int)(idx % 3456); int pix = (int)(idx / 3456);
    int c = j % 384; int kk = j / 384;
    int ky = kk / 3, kx = kk % 3;
    int w = pix % 28; int t = pix / 28;
    int h = t % 28; int b = t / 28;
    int hh = h + ky - 1, ww = w + kx - 1;
    float val = 0.f;
    if ((unsigned)hh < 28u && (unsigned)ww < 28u)
        val = in[(((size_t)b * 28 + hh) * 28 + ww) * 384 + c];
    out[idx] = val;
}

// ---------------- MHA: one warp per query, K/V staged in dynamic smem ----------------
__global__ void mha_kernel(const float* __restrict__ q, int qs,
                           const float* __restrict__ k, int ks,
                           const float* __restrict__ v, int vs,
                           float* __restrict__ o, int os,
                           int Nq, int Nk)
{
    extern __shared__ float sm[];
    float* ksh = sm;
    float* vsh = sm + (size_t)Nk * 64;
    float* ssc = vsh + (size_t)Nk * 64;
    const int bh = blockIdx.x;
    const int b = bh / 6, h = bh % 6;
    const int tid = threadIdx.x;
    const int warp = tid >> 5, lane = tid & 31;
    const float* kb = k + (size_t)b * Nk * ks + h * 64;
    const float* vb = v + (size_t)b * Nk * vs + h * 64;
    for (int idx = tid; idx < Nk * 64; idx += blockDim.x) {
        int j = idx >> 6, d = idx & 63;
        ksh[idx] = kb[(size_t)j * ks + d];
        vsh[idx] = vb[(size_t)j * vs + d];
    }
    __syncthreads();
    const int nw = blockDim.x >> 5;
    float* sc = ssc + warp * Nk;
    const int d0 = lane << 1;
    for (int qi = blockIdx.y * nw + warp; qi < Nq; qi += gridDim.y * nw) {
        const float* qr = q + ((size_t)b * Nq + qi) * qs + h * 64;
        float q0 = qr[d0] * 0.125f, q1 = qr[d0 + 1] * 0.125f;
        float mx = -1e30f;
        for (int j = 0; j < Nk; j++) {
            float s = fmaf(q0, ksh[(j << 6) + d0], q1 * ksh[(j << 6) + d0 + 1]);
            #pragma unroll
            for (int off = 16; off; off >>= 1) s += __shfl_xor_sync(0xffffffffu, s, off);
            if (lane == (j & 31)) sc[j] = s;
            mx = fmaxf(mx, s);
        }
        __syncwarp();
        float sume = 0.f;
        for (int j = lane; j < Nk; j += 32) {
            float e = expf(sc[j] - mx);
            sc[j] = e; sume += e;
        }
        #pragma unroll
        for (int off = 16; off; off >>= 1) sume += __shfl_xor_sync(0xffffffffu, sume, off);
        float inv = 1.f / sume;
        __syncwarp();
        float o0 = 0.f, o1 = 0.f;
        for (int j = 0; j < Nk; j++) {
            float p = sc[j];
            o0 = fmaf(p, vsh[(j << 6) + d0], o0);
            o1 = fmaf(p, vsh[(j << 6) + d0 + 1], o1);
        }
        float* orow = o + ((size_t)b * Nq + qi) * os + h * 64;
        orow[d0] = o0 * inv;
        orow[d0 + 1] = o1 * inv;
        __syncwarp();
    }
}

// ---------------- launch ----------------
extern "C" void kernel_launch(void* const* d_in, const int* in_sizes, int n_in,
                              void* d_out, int out_size)
{
    const float* x        = (const float*)d_in[0];
    const float* gtok     = (const float*)d_in[1];
    const float* we_dw_w  = (const float*)d_in[2];
    const float* we_dw_b  = (const float*)d_in[3];
    const float* we_ln_g  = (const float*)d_in[4];
    const float* we_ln_b  = (const float*)d_in[5];
    const float* we_pw1_w = (const float*)d_in[6];
    const float* we_pw1_b = (const float*)d_in[7];
    const float* we_pw2_w = (const float*)d_in[8];
    const float* we_pw2_b = (const float*)d_in[9];
    const float* we_gamma = (const float*)d_in[10];
    const float* cb_conv_w= (const float*)d_in[11];
    const float* cb_ln_g  = (const float*)d_in[12];
    const float* cb_ln_b  = (const float*)d_in[13];
    const float* ga_qkv_w = (const float*)d_in[14];
    const float* ug_kv_w  = (const float*)d_in[15];
    const float* ug_q_w   = (const float*)d_in[16];
    const float* gb_kv_w  = (const float*)d_in[17];
    const float* gb_q_w   = (const float*)d_in[18];
    const float* proj_w   = (const float*)d_in[19];
    const float* proj_b   = (const float*)d_in[20];

    float* out = (float*)d_out;
    float* gt_out = out + GT_OFF;

    float *ln1, *h1, *xlocal, *pool1, *col, *c2pre, *c2, *xd, *qkv, *xds, *kv2, *qg, *kv3, *qx;
    float *pw1T, *pw2T, *qkvT, *ugkvT, *ugqT, *gbkvT, *gbqT, *projT, *convT;
    cudaGetSymbolAddress((void**)&ln1,    g_ln1);
    cudaGetSymbolAddress((void**)&h1,     g_h1);
    cudaGetSymbolAddress((void**)&xlocal, g_xlocal);
    cudaGetSymbolAddress((void**)&pool1,  g_pool1);
    cudaGetSymbolAddress((void**)&col,    g_col);
    cudaGetSymbolAddress((void**)&c2pre,  g_c2pre);
    cudaGetSymbolAddress((void**)&c2,     g_c2);
    cudaGetSymbolAddress((void**)&xd,     g_xd);
    cudaGetSymbolAddress((void**)&qkv,    g_qkv);
    cudaGetSymbolAddress((void**)&xds,    g_xds);
    cudaGetSymbolAddress((void**)&kv2,    g_kv2);
    cudaGetSymbolAddress((void**)&qg,     g_qg);
    cudaGetSymbolAddress((void**)&kv3,    g_kv3);
    cudaGetSymbolAddress((void**)&qx,     g_qx);
    cudaGetSymbolAddress((void**)&pw1T,   g_pw1T);
    cudaGetSymbolAddress((void**)&pw2T,   g_pw2T);
    cudaGetSymbolAddress((void**)&qkvT,   g_qkvT);
    cudaGetSymbolAddress((void**)&ugkvT,  g_ugkvT);
    cudaGetSymbolAddress((void**)&ugqT,   g_ugqT);
    cudaGetSymbolAddress((void**)&gbkvT,  g_gbkvT);
    cudaGetSymbolAddress((void**)&gbqT,   g_gbqT);
    cudaGetSymbolAddress((void**)&projT,  g_projT);
    cudaGetSymbolAddress((void**)&convT,  g_convT);
    float* xglobal = h1;   // reuse MLP hidden buffer (free after MLP2)

    const int SMEM196 = 196 * 128 * 4 + 4 * 196 * 4;  // 103488 B
    const int SMEM49  = 49  * 128 * 4 + 4 * 49  * 4;  // 25872  B
    cudaFuncSetAttribute(mha_kernel, cudaFuncAttributeMaxDynamicSharedMemorySize, SMEM196);

    // ---- weight transposes (tiny) ----
    transpose_kernel<<<(589824 + 255) / 256, 256>>>(we_pw1_w, pw1T, 384, 1536);
    transpose_kernel<<<(589824 + 255) / 256, 256>>>(we_pw2_w, pw2T, 1536, 384);
    transpose_kernel<<<(442368 + 255) / 256, 256>>>(ga_qkv_w, qkvT, 384, 1152);
    transpose_kernel<<<(294912 + 255) / 256, 256>>>(ug_kv_w, ugkvT, 384, 768);
    transpose_kernel<<<(147456 + 255) / 256, 256>>>(ug_q_w,  ugqT,  384, 384);
    transpose_kernel<<<(294912 + 255) / 256, 256>>>(gb_kv_w, gbkvT, 384, 768);
    transpose_kernel<<<(147456 + 255) / 256, 256>>>(gb_q_w,  gbqT,  384, 384);
    transpose_kernel<<<(147456 + 255) / 256, 256>>>(proj_w,  projT, 384, 384);
    convw_trans_kernel<<<(1327104 + 255) / 256, 256>>>(cb_conv_w, convT);

    // ConvEncoder: dwconv + LN
    dwconv_ln_kernel<<<50176, 128>>>(x, we_dw_w, we_dw_b, we_ln_g, we_ln_b, ln1);

    // MLP1: gelu(ln1 @ pw1 + b1)
    tgemm_kernel<2><<<dim3(12, 392), 256>>>(ln1, nullptr, pw1T, we_pw1_b,
                                            nullptr, nullptr, h1, 50176, 1536, 384);
    // MLP2 + layer-scale + residual
    tgemm_kernel<3><<<dim3(3, 392), 256>>>(h1, nullptr, pw2T, we_pw2_b,
                                           we_gamma, x, xlocal, 50176, 384, 1536);
    // down_1: 56->28
    avgpool2_kernel<<<(4816896 + 255) / 256, 256>>>(xlocal, pool1, 16, 28, 28);

    // ConvBNReLU: im2col + GEMM + LN(1e-5) + ReLU
    im2col_kernel<<<(int)((12544LL * 3456 + 255) / 256), 256>>>(pool1, col);
    tgemm_kernel<0><<<dim3(3, 98), 256>>>(col, nullptr, convT, nullptr, nullptr, nullptr,
                                          c2pre, 12544, 384, 3456);
    ln_act_kernel<<<12544, 128>>>(c2pre, cb_ln_g, cb_ln_b, c2, 1e-5f, 1);

    // down_2: 28->14
    avgpool2_kernel<<<(1204224 + 255) / 256, 256>>>(c2, xd, 16, 14, 14);

    // global aggregation MHSA
    tgemm_kernel<0><<<dim3(9, 25), 256>>>(xd, nullptr, qkvT, nullptr, nullptr, nullptr,
                                          qkv, 3136, 1152, 384);
    mha_kernel<<<dim3(96, 8), 128, SMEM196>>>(qkv, 1152, qkv + 384, 1152, qkv + 768, 1152,
                                              xds, 384, 196, 196);

    // global token update
    tgemm_kernel<0><<<dim3(6, 25), 256>>>(xds, nullptr, ugkvT, nullptr, nullptr, nullptr,
                                          kv2, 3136, 768, 384);
    tgemm_kernel<0><<<dim3(3, 7), 256>>>(gtok, nullptr, ugqT, nullptr, nullptr, nullptr,
                                         qg, 784, 384, 384);
    mha_kernel<<<dim3(96, 2), 128, SMEM196>>>(qg, 384, kv2, 768, kv2 + 384, 768,
                                              gt_out, 384, 49, 196);

    // global broadcast
    tgemm_kernel<0><<<dim3(6, 7), 256>>>(gt_out, nullptr, gbkvT, nullptr, nullptr, nullptr,
                                         kv3, 784, 768, 384);
    tgemm_kernel<0><<<dim3(3, 392), 256>>>(x, nullptr, gbqT, nullptr, nullptr, nullptr,
                                           qx, 50176, 384, 384);
    mha_kernel<<<dim3(96, 64), 128, SMEM49>>>(qx, 384, kv3, 768, kv3 + 384, 768,
                                              xglobal, 384, 3136, 49);

    // final projection
    tgemm_kernel<4><<<dim3(3, 392), 256>>>(xlocal, xglobal, projT, proj_b,
                                           nullptr, nullptr, out, 50176, 384, 384);
}